// round 4
// baseline (speedup 1.0000x reference)
#include <cuda_runtime.h>

#define LL 8
#define KK 8
#define NN 1048576
#define GBLK 128            // gram blocks per layer
#define OBLK 256            // output blocks per layer
#define NPAIR 36            // upper-triangular 8x8 pairs

// Deterministic reduction scratch (no device mallocs allowed).
__device__ float g_part[LL][GBLK][NPAIR];
__device__ float g_w[LL][KK * KK];

// ---------------------------------------------------------------------------
// Kernel 1: per-block partial Gram sums (upper triangle incl. diagonal).
// float2 loads + 2-stage software pipeline to cut registers (occ 2->3 CTA/SM)
// and overlap DRAM latency with the FFMA block. Deterministic reduction order.
// grid = (GBLK, LL), block = 256.
// ---------------------------------------------------------------------------
__global__ __launch_bounds__(256, 3) void gram_kernel(const float* __restrict__ deltas) {
    const int layer = blockIdx.y;
    const float2* __restrict__ base =
        reinterpret_cast<const float2*>(deltas + (size_t)layer * KK * NN);
    const int tid = threadIdx.x;

    float acc[NPAIR];
#pragma unroll
    for (int p = 0; p < NPAIR; p++) acc[p] = 0.0f;

    const int R2 = NN / 2;                // float2 per row = 524288
    const int stride = GBLK * 256;        // 32768 float2 per sweep
    const int iters = R2 / stride;        // 16 (even)
    const int n0 = blockIdx.x * 256 + tid;

    float2 cur[KK], nxt[KK];
#pragma unroll
    for (int j = 0; j < KK; j++) cur[j] = base[(size_t)j * R2 + n0];

    for (int it = 0; it < iters; it += 2) {
        // prefetch it+1 (always valid: iters even)
        {
            const int n = n0 + (it + 1) * stride;
#pragma unroll
            for (int j = 0; j < KK; j++) nxt[j] = base[(size_t)j * R2 + n];
        }
        // compute on cur (iteration it)
        {
            int p = 0;
#pragma unroll
            for (int i = 0; i < KK; i++)
#pragma unroll
                for (int j = i; j < KK; j++) {
                    acc[p] += cur[i].x * cur[j].x + cur[i].y * cur[j].y;
                    p++;
                }
        }
        // prefetch it+2 into cur (guarded)
        if (it + 2 < iters) {
            const int n = n0 + (it + 2) * stride;
#pragma unroll
            for (int j = 0; j < KK; j++) cur[j] = base[(size_t)j * R2 + n];
        }
        // compute on nxt (iteration it+1)
        {
            int p = 0;
#pragma unroll
            for (int i = 0; i < KK; i++)
#pragma unroll
                for (int j = i; j < KK; j++) {
                    acc[p] += nxt[i].x * nxt[j].x + nxt[i].y * nxt[j].y;
                    p++;
                }
        }
    }

    // Warp-level reduce each of the 36 accumulators.
#pragma unroll
    for (int p = 0; p < NPAIR; p++) {
        float a = acc[p];
#pragma unroll
        for (int o = 16; o > 0; o >>= 1)
            a += __shfl_down_sync(0xffffffffu, a, o);
        acc[p] = a;
    }

    __shared__ float s[8][NPAIR];
    const int wid = tid >> 5, lane = tid & 31;
    if (lane == 0) {
#pragma unroll
        for (int p = 0; p < NPAIR; p++) s[wid][p] = acc[p];
    }
    __syncthreads();

    if (tid < NPAIR) {
        float a = 0.0f;
#pragma unroll
        for (int w = 0; w < 8; w++) a += s[w][tid];
        g_part[layer][blockIdx.x][tid] = a;
    }
}

// ---------------------------------------------------------------------------
// Kernel 2: reduce partials -> logits -> softmax -> W = clip(beta)*attn + I.
// grid = LL, block = 64. Tiny.
// ---------------------------------------------------------------------------
__global__ __launch_bounds__(64) void finish_kernel(const float* __restrict__ beta) {
    const int layer = blockIdx.x;
    const int tid = threadIdx.x;
    __shared__ float gram[NPAIR];

    if (tid < NPAIR) {
        float a = 0.0f;
        for (int b = 0; b < GBLK; b++) a += g_part[layer][b][tid];
        gram[tid] = a;
    }
    __syncthreads();

    if (tid < KK) {
        const int k = tid;
        const float scale = rsqrtf((float)NN);   // N^-0.5
        float row[KK];
#pragma unroll
        for (int j = 0; j < KK; j++) {
            const int a = (k < j) ? k : j;
            const int b = (k < j) ? j : k;
            const int p = a * KK - (a * (a - 1)) / 2 + (b - a);
            row[j] = gram[p] * scale;
        }
        float m = row[0];
#pragma unroll
        for (int j = 1; j < KK; j++) m = fmaxf(m, row[j]);
        float s = 0.0f;
#pragma unroll
        for (int j = 0; j < KK; j++) { row[j] = expf(row[j] - m); s += row[j]; }
        const float inv = 1.0f / s;
        float b = beta[layer * KK + k];
        b = fminf(fmaxf(b, 0.0f), 1.0f);
#pragma unroll
        for (int j = 0; j < KK; j++)
            g_w[layer][k * KK + j] = b * row[j] * inv + ((j == k) ? 1.0f : 0.0f);
    }
}

// ---------------------------------------------------------------------------
// Kernel 3: out[l,k,n] = last[l,k,n] + sum_j W[l,k,j] * deltas[l,j,n]
// Processes n-chunks in DESCENDING order: gram just finished streaming the
// high-n tail of deltas, so those re-reads hit L2. `last` loads use __ldcs
// and out stores use __stcs (streaming / evict-first) so single-use traffic
// doesn't evict the reusable deltas lines.
// grid = (OBLK, LL), block = 256, float4 streaming.
// ---------------------------------------------------------------------------
__global__ __launch_bounds__(256) void out_kernel(const float* __restrict__ last,
                                                  const float* __restrict__ deltas,
                                                  float* __restrict__ out) {
    const int layer = blockIdx.y;
    __shared__ float w[KK * KK];
    const int tid = threadIdx.x;
    if (tid < KK * KK) w[tid] = g_w[layer][tid];
    __syncthreads();

    const size_t off = (size_t)layer * KK * NN;
    const float4* __restrict__ d4 = reinterpret_cast<const float4*>(deltas + off);
    const float4* __restrict__ l4 = reinterpret_cast<const float4*>(last + off);
    float4* __restrict__ o4 = reinterpret_cast<float4*>(out + off);

    const int R = NN / 4;                 // 262144
    const int stride = OBLK * 256;        // 65536
    const int iters = R / stride;         // 4
    const int idx = blockIdx.x * 256 + tid;

#pragma unroll
    for (int it = iters - 1; it >= 0; it--) {   // descending chunks: hit L2 tail
        const int n4 = idx + it * stride;
        float4 d[KK];
#pragma unroll
        for (int j = 0; j < KK; j++)
            d[j] = d4[(size_t)j * R + n4];

#pragma unroll
        for (int k = 0; k < KK; k++) {
            float4 acc = __ldcs(&l4[(size_t)k * R + n4]);
#pragma unroll
            for (int j = 0; j < KK; j++) {
                const float wv = w[k * KK + j];
                acc.x = fmaf(wv, d[j].x, acc.x);
                acc.y = fmaf(wv, d[j].y, acc.y);
                acc.z = fmaf(wv, d[j].z, acc.z);
                acc.w = fmaf(wv, d[j].w, acc.w);
            }
            __stcs(&o4[(size_t)k * R + n4], acc);
        }
    }
}

extern "C" void kernel_launch(void* const* d_in, const int* in_sizes, int n_in,
                              void* d_out, int out_size) {
    const float* last   = (const float*)d_in[0];
    const float* deltas = (const float*)d_in[1];
    const float* beta   = (const float*)d_in[2];
    float* out = (float*)d_out;

    dim3 ggrid(GBLK, LL);
    gram_kernel<<<ggrid, 256>>>(deltas);

    finish_kernel<<<LL, 64>>>(beta);

    dim3 ogrid(OBLK, LL);
    out_kernel<<<ogrid, 256>>>(last, deltas, out);
}

// round 5
// speedup vs baseline: 1.1311x; 1.1311x over previous
#include <cuda_runtime.h>

#define LL 8
#define KK 8
#define NN 1048576
#define GBLK 128            // gram blocks per layer
#define OBLK 256            // output blocks per layer
#define NPAIR 36            // upper-triangular 8x8 pairs

// Deterministic reduction scratch (no device mallocs allowed).
__device__ float g_part[LL][GBLK][NPAIR];
__device__ float g_w[LL][KK * KK];

// ---------------------------------------------------------------------------
// Kernel 1: per-block partial Gram sums (upper triangle incl. diagonal).
// float2 loads, NO manual pipeline: keep regs <= 64 so we get 4 CTAs/SM
// (32 warps) and let HW warp interleaving cover DRAM latency (MLP=8 batched
// loads per warp per iteration). Deterministic reduction order.
// grid = (GBLK, LL), block = 256.
// ---------------------------------------------------------------------------
__global__ __launch_bounds__(256, 4) void gram_kernel(const float* __restrict__ deltas) {
    const int layer = blockIdx.y;
    const float2* __restrict__ base =
        reinterpret_cast<const float2*>(deltas + (size_t)layer * KK * NN);
    const int tid = threadIdx.x;

    float acc[NPAIR];
#pragma unroll
    for (int p = 0; p < NPAIR; p++) acc[p] = 0.0f;

    const int R2 = NN / 2;                // float2 per row = 524288
    const int stride = GBLK * 256;        // 32768 float2 per sweep
    const int iters = R2 / stride;        // 16
    const int n0 = blockIdx.x * 256 + tid;

    for (int it = 0; it < iters; it++) {
        const int n = n0 + it * stride;
        float2 v[KK];
#pragma unroll
        for (int j = 0; j < KK; j++)
            v[j] = base[(size_t)j * R2 + n];

        int p = 0;
#pragma unroll
        for (int i = 0; i < KK; i++)
#pragma unroll
            for (int j = i; j < KK; j++) {
                acc[p] += v[i].x * v[j].x + v[i].y * v[j].y;
                p++;
            }
    }

    // Warp-level reduce each of the 36 accumulators.
#pragma unroll
    for (int p = 0; p < NPAIR; p++) {
        float a = acc[p];
#pragma unroll
        for (int o = 16; o > 0; o >>= 1)
            a += __shfl_down_sync(0xffffffffu, a, o);
        acc[p] = a;
    }

    __shared__ float s[8][NPAIR];
    const int wid = tid >> 5, lane = tid & 31;
    if (lane == 0) {
#pragma unroll
        for (int p = 0; p < NPAIR; p++) s[wid][p] = acc[p];
    }
    __syncthreads();

    if (tid < NPAIR) {
        float a = 0.0f;
#pragma unroll
        for (int w = 0; w < 8; w++) a += s[w][tid];
        g_part[layer][blockIdx.x][tid] = a;
    }
}

// ---------------------------------------------------------------------------
// Kernel 2: reduce partials -> logits -> softmax -> W = clip(beta)*attn + I.
// grid = LL, block = 64. Tiny.
// ---------------------------------------------------------------------------
__global__ __launch_bounds__(64) void finish_kernel(const float* __restrict__ beta) {
    const int layer = blockIdx.x;
    const int tid = threadIdx.x;
    __shared__ float gram[NPAIR];

    if (tid < NPAIR) {
        float a = 0.0f;
        for (int b = 0; b < GBLK; b++) a += g_part[layer][b][tid];
        gram[tid] = a;
    }
    __syncthreads();

    if (tid < KK) {
        const int k = tid;
        const float scale = rsqrtf((float)NN);   // N^-0.5
        float row[KK];
#pragma unroll
        for (int j = 0; j < KK; j++) {
            const int a = (k < j) ? k : j;
            const int b = (k < j) ? j : k;
            const int p = a * KK - (a * (a - 1)) / 2 + (b - a);
            row[j] = gram[p] * scale;
        }
        float m = row[0];
#pragma unroll
        for (int j = 1; j < KK; j++) m = fmaxf(m, row[j]);
        float s = 0.0f;
#pragma unroll
        for (int j = 0; j < KK; j++) { row[j] = expf(row[j] - m); s += row[j]; }
        const float inv = 1.0f / s;
        float b = beta[layer * KK + k];
        b = fminf(fmaxf(b, 0.0f), 1.0f);
#pragma unroll
        for (int j = 0; j < KK; j++)
            g_w[layer][k * KK + j] = b * row[j] * inv + ((j == k) ? 1.0f : 0.0f);
    }
}

// ---------------------------------------------------------------------------
// Kernel 3: out[l,k,n] = last[l,k,n] + sum_j W[l,k,j] * deltas[l,j,n]
// R3 version (fastest so far): ascending chunks, plain loads/stores.
// grid = (OBLK, LL), block = 256, float4 streaming.
// ---------------------------------------------------------------------------
__global__ __launch_bounds__(256) void out_kernel(const float* __restrict__ last,
                                                  const float* __restrict__ deltas,
                                                  float* __restrict__ out) {
    const int layer = blockIdx.y;
    __shared__ float w[KK * KK];
    const int tid = threadIdx.x;
    if (tid < KK * KK) w[tid] = g_w[layer][tid];
    __syncthreads();

    const size_t off = (size_t)layer * KK * NN;
    const float4* __restrict__ d4 = reinterpret_cast<const float4*>(deltas + off);
    const float4* __restrict__ l4 = reinterpret_cast<const float4*>(last + off);
    float4* __restrict__ o4 = reinterpret_cast<float4*>(out + off);

    const int R = NN / 4;                 // 262144
    const int stride = OBLK * 256;        // 65536
    int idx = blockIdx.x * 256 + tid;

#pragma unroll
    for (int it = 0; it < R / stride; it++) {   // 4 iterations
        const int n4 = idx + it * stride;
        float4 d[KK];
#pragma unroll
        for (int j = 0; j < KK; j++)
            d[j] = d4[(size_t)j * R + n4];

#pragma unroll
        for (int k = 0; k < KK; k++) {
            float4 acc = l4[(size_t)k * R + n4];
#pragma unroll
            for (int j = 0; j < KK; j++) {
                const float wv = w[k * KK + j];
                acc.x = fmaf(wv, d[j].x, acc.x);
                acc.y = fmaf(wv, d[j].y, acc.y);
                acc.z = fmaf(wv, d[j].z, acc.z);
                acc.w = fmaf(wv, d[j].w, acc.w);
            }
            o4[(size_t)k * R + n4] = acc;
        }
    }
}

extern "C" void kernel_launch(void* const* d_in, const int* in_sizes, int n_in,
                              void* d_out, int out_size) {
    const float* last   = (const float*)d_in[0];
    const float* deltas = (const float*)d_in[1];
    const float* beta   = (const float*)d_in[2];
    float* out = (float*)d_out;

    dim3 ggrid(GBLK, LL);
    gram_kernel<<<ggrid, 256>>>(deltas);

    finish_kernel<<<LL, 64>>>(beta);

    dim3 ogrid(OBLK, LL);
    out_kernel<<<ogrid, 256>>>(last, deltas, out);
}

// round 6
// speedup vs baseline: 1.1870x; 1.0494x over previous
#include <cuda_runtime.h>

#define LL 8
#define KK 8
#define NN 1048576
#define GBLK 128            // gram blocks per layer
#define OBLK 256            // output blocks per layer
#define NPAIR 36            // upper-triangular 8x8 pairs

// Deterministic reduction scratch (no device mallocs allowed).
__device__ float g_part[LL][GBLK][NPAIR];
__device__ float g_w[LL][KK * KK];

// ---------------------------------------------------------------------------
// Kernel 1: per-block partial Gram sums (upper triangle incl. diagonal).
// float4 loads + 2-stage software pipeline: 16 outstanding LDG.128 per warp
// (8KB/warp, 128KB/SM at 2 CTAs) — maximize bytes-in-flight, which R3/R4/R5
// showed is what HBM throughput tracks. Deterministic reduction order.
// grid = (GBLK, LL), block = 256.
// ---------------------------------------------------------------------------
__global__ __launch_bounds__(256, 2) void gram_kernel(const float* __restrict__ deltas) {
    const int layer = blockIdx.y;
    const float4* __restrict__ base =
        reinterpret_cast<const float4*>(deltas + (size_t)layer * KK * NN);
    const int tid = threadIdx.x;

    float acc[NPAIR];
#pragma unroll
    for (int p = 0; p < NPAIR; p++) acc[p] = 0.0f;

    const int R4 = NN / 4;                // float4 per row = 262144
    const int stride = GBLK * 256;        // 32768 float4 per sweep
    const int iters = R4 / stride;        // 8 (even)
    const int n0 = blockIdx.x * 256 + tid;

    float4 cur[KK], nxt[KK];
#pragma unroll
    for (int j = 0; j < KK; j++) cur[j] = base[(size_t)j * R4 + n0];

    for (int it = 0; it < iters; it += 2) {
        // prefetch it+1 (always valid: iters even)
        {
            const int n = n0 + (it + 1) * stride;
#pragma unroll
            for (int j = 0; j < KK; j++) nxt[j] = base[(size_t)j * R4 + n];
        }
        // compute on cur
        {
            int p = 0;
#pragma unroll
            for (int i = 0; i < KK; i++)
#pragma unroll
                for (int j = i; j < KK; j++) {
                    acc[p] += cur[i].x * cur[j].x + cur[i].y * cur[j].y +
                              cur[i].z * cur[j].z + cur[i].w * cur[j].w;
                    p++;
                }
        }
        // prefetch it+2 into cur (guarded)
        if (it + 2 < iters) {
            const int n = n0 + (it + 2) * stride;
#pragma unroll
            for (int j = 0; j < KK; j++) cur[j] = base[(size_t)j * R4 + n];
        }
        // compute on nxt
        {
            int p = 0;
#pragma unroll
            for (int i = 0; i < KK; i++)
#pragma unroll
                for (int j = i; j < KK; j++) {
                    acc[p] += nxt[i].x * nxt[j].x + nxt[i].y * nxt[j].y +
                              nxt[i].z * nxt[j].z + nxt[i].w * nxt[j].w;
                    p++;
                }
        }
    }

    // Warp-level reduce each of the 36 accumulators.
#pragma unroll
    for (int p = 0; p < NPAIR; p++) {
        float a = acc[p];
#pragma unroll
        for (int o = 16; o > 0; o >>= 1)
            a += __shfl_down_sync(0xffffffffu, a, o);
        acc[p] = a;
    }

    __shared__ float s[8][NPAIR];
    const int wid = tid >> 5, lane = tid & 31;
    if (lane == 0) {
#pragma unroll
        for (int p = 0; p < NPAIR; p++) s[wid][p] = acc[p];
    }
    __syncthreads();

    if (tid < NPAIR) {
        float a = 0.0f;
#pragma unroll
        for (int w = 0; w < 8; w++) a += s[w][tid];
        g_part[layer][blockIdx.x][tid] = a;
    }
}

// ---------------------------------------------------------------------------
// Kernel 2: reduce partials -> logits -> softmax -> W = clip(beta)*attn + I.
// grid = LL, block = 64. Tiny.
// ---------------------------------------------------------------------------
__global__ __launch_bounds__(64) void finish_kernel(const float* __restrict__ beta) {
    const int layer = blockIdx.x;
    const int tid = threadIdx.x;
    __shared__ float gram[NPAIR];

    if (tid < NPAIR) {
        float a = 0.0f;
        for (int b = 0; b < GBLK; b++) a += g_part[layer][b][tid];
        gram[tid] = a;
    }
    __syncthreads();

    if (tid < KK) {
        const int k = tid;
        const float scale = rsqrtf((float)NN);   // N^-0.5
        float row[KK];
#pragma unroll
        for (int j = 0; j < KK; j++) {
            const int a = (k < j) ? k : j;
            const int b = (k < j) ? j : k;
            const int p = a * KK - (a * (a - 1)) / 2 + (b - a);
            row[j] = gram[p] * scale;
        }
        float m = row[0];
#pragma unroll
        for (int j = 1; j < KK; j++) m = fmaxf(m, row[j]);
        float s = 0.0f;
#pragma unroll
        for (int j = 0; j < KK; j++) { row[j] = expf(row[j] - m); s += row[j]; }
        const float inv = 1.0f / s;
        float b = beta[layer * KK + k];
        b = fminf(fmaxf(b, 0.0f), 1.0f);
#pragma unroll
        for (int j = 0; j < KK; j++)
            g_w[layer][k * KK + j] = b * row[j] * inv + ((j == k) ? 1.0f : 0.0f);
    }
}

// ---------------------------------------------------------------------------
// Kernel 3: out[l,k,n] = last[l,k,n] + sum_j W[l,k,j] * deltas[l,j,n]
// R3 version (fastest so far): ascending chunks, plain loads/stores.
// grid = (OBLK, LL), block = 256, float4 streaming.
// ---------------------------------------------------------------------------
__global__ __launch_bounds__(256) void out_kernel(const float* __restrict__ last,
                                                  const float* __restrict__ deltas,
                                                  float* __restrict__ out) {
    const int layer = blockIdx.y;
    __shared__ float w[KK * KK];
    const int tid = threadIdx.x;
    if (tid < KK * KK) w[tid] = g_w[layer][tid];
    __syncthreads();

    const size_t off = (size_t)layer * KK * NN;
    const float4* __restrict__ d4 = reinterpret_cast<const float4*>(deltas + off);
    const float4* __restrict__ l4 = reinterpret_cast<const float4*>(last + off);
    float4* __restrict__ o4 = reinterpret_cast<float4*>(out + off);

    const int R = NN / 4;                 // 262144
    const int stride = OBLK * 256;        // 65536
    int idx = blockIdx.x * 256 + tid;

#pragma unroll
    for (int it = 0; it < R / stride; it++) {   // 4 iterations
        const int n4 = idx + it * stride;
        float4 d[KK];
#pragma unroll
        for (int j = 0; j < KK; j++)
            d[j] = d4[(size_t)j * R + n4];

#pragma unroll
        for (int k = 0; k < KK; k++) {
            float4 acc = l4[(size_t)k * R + n4];
#pragma unroll
            for (int j = 0; j < KK; j++) {
                const float wv = w[k * KK + j];
                acc.x = fmaf(wv, d[j].x, acc.x);
                acc.y = fmaf(wv, d[j].y, acc.y);
                acc.z = fmaf(wv, d[j].z, acc.z);
                acc.w = fmaf(wv, d[j].w, acc.w);
            }
            o4[(size_t)k * R + n4] = acc;
        }
    }
}

extern "C" void kernel_launch(void* const* d_in, const int* in_sizes, int n_in,
                              void* d_out, int out_size) {
    const float* last   = (const float*)d_in[0];
    const float* deltas = (const float*)d_in[1];
    const float* beta   = (const float*)d_in[2];
    float* out = (float*)d_out;

    dim3 ggrid(GBLK, LL);
    gram_kernel<<<ggrid, 256>>>(deltas);

    finish_kernel<<<LL, 64>>>(beta);

    dim3 ogrid(OBLK, LL);
    out_kernel<<<ogrid, 256>>>(last, deltas, out);
}

// round 7
// speedup vs baseline: 1.1965x; 1.0080x over previous
#include <cuda_runtime.h>

#define LL 8
#define KK 8
#define NN 1048576
#define GBLK 128            // gram blocks per layer
#define OBLK 256            // output blocks per layer
#define NPAIR 36            // upper-triangular 8x8 pairs

// Deterministic reduction scratch (no device mallocs allowed).
__device__ float g_part[LL][GBLK][NPAIR];
__device__ float g_w[LL][KK * KK];

// ---------------------------------------------------------------------------
// Kernel 1: per-block partial Gram sums (upper triangle incl. diagonal).
// float4 loads + 2-stage software pipeline: 16 outstanding LDG.128 per warp
// (8KB/warp, 128KB/SM at 2 CTAs) — best measured variant (47.9us, 5.7TB/s).
// grid = (GBLK, LL), block = 256.
// ---------------------------------------------------------------------------
__global__ __launch_bounds__(256, 2) void gram_kernel(const float* __restrict__ deltas) {
    const int layer = blockIdx.y;
    const float4* __restrict__ base =
        reinterpret_cast<const float4*>(deltas + (size_t)layer * KK * NN);
    const int tid = threadIdx.x;

    float acc[NPAIR];
#pragma unroll
    for (int p = 0; p < NPAIR; p++) acc[p] = 0.0f;

    const int R4 = NN / 4;                // float4 per row = 262144
    const int stride = GBLK * 256;        // 32768 float4 per sweep
    const int iters = R4 / stride;        // 8 (even)
    const int n0 = blockIdx.x * 256 + tid;

    float4 cur[KK], nxt[KK];
#pragma unroll
    for (int j = 0; j < KK; j++) cur[j] = base[(size_t)j * R4 + n0];

    for (int it = 0; it < iters; it += 2) {
        // prefetch it+1 (always valid: iters even)
        {
            const int n = n0 + (it + 1) * stride;
#pragma unroll
            for (int j = 0; j < KK; j++) nxt[j] = base[(size_t)j * R4 + n];
        }
        // compute on cur
        {
            int p = 0;
#pragma unroll
            for (int i = 0; i < KK; i++)
#pragma unroll
                for (int j = i; j < KK; j++) {
                    acc[p] += cur[i].x * cur[j].x + cur[i].y * cur[j].y +
                              cur[i].z * cur[j].z + cur[i].w * cur[j].w;
                    p++;
                }
        }
        // prefetch it+2 into cur (guarded)
        if (it + 2 < iters) {
            const int n = n0 + (it + 2) * stride;
#pragma unroll
            for (int j = 0; j < KK; j++) cur[j] = base[(size_t)j * R4 + n];
        }
        // compute on nxt
        {
            int p = 0;
#pragma unroll
            for (int i = 0; i < KK; i++)
#pragma unroll
                for (int j = i; j < KK; j++) {
                    acc[p] += nxt[i].x * nxt[j].x + nxt[i].y * nxt[j].y +
                              nxt[i].z * nxt[j].z + nxt[i].w * nxt[j].w;
                    p++;
                }
        }
    }

    // Warp-level reduce each of the 36 accumulators.
#pragma unroll
    for (int p = 0; p < NPAIR; p++) {
        float a = acc[p];
#pragma unroll
        for (int o = 16; o > 0; o >>= 1)
            a += __shfl_down_sync(0xffffffffu, a, o);
        acc[p] = a;
    }

    __shared__ float s[8][NPAIR];
    const int wid = tid >> 5, lane = tid & 31;
    if (lane == 0) {
#pragma unroll
        for (int p = 0; p < NPAIR; p++) s[wid][p] = acc[p];
    }
    __syncthreads();

    if (tid < NPAIR) {
        float a = 0.0f;
#pragma unroll
        for (int w = 0; w < 8; w++) a += s[w][tid];
        g_part[layer][blockIdx.x][tid] = a;
    }
}

// ---------------------------------------------------------------------------
// Kernel 2: reduce partials -> logits -> softmax -> W = clip(beta)*attn + I.
// grid = LL, block = 64. Tiny.
// ---------------------------------------------------------------------------
__global__ __launch_bounds__(64) void finish_kernel(const float* __restrict__ beta) {
    const int layer = blockIdx.x;
    const int tid = threadIdx.x;
    __shared__ float gram[NPAIR];

    if (tid < NPAIR) {
        float a = 0.0f;
        for (int b = 0; b < GBLK; b++) a += g_part[layer][b][tid];
        gram[tid] = a;
    }
    __syncthreads();

    if (tid < KK) {
        const int k = tid;
        const float scale = rsqrtf((float)NN);   // N^-0.5
        float row[KK];
#pragma unroll
        for (int j = 0; j < KK; j++) {
            const int a = (k < j) ? k : j;
            const int b = (k < j) ? j : k;
            const int p = a * KK - (a * (a - 1)) / 2 + (b - a);
            row[j] = gram[p] * scale;
        }
        float m = row[0];
#pragma unroll
        for (int j = 1; j < KK; j++) m = fmaxf(m, row[j]);
        float s = 0.0f;
#pragma unroll
        for (int j = 0; j < KK; j++) { row[j] = expf(row[j] - m); s += row[j]; }
        const float inv = 1.0f / s;
        float b = beta[layer * KK + k];
        b = fminf(fmaxf(b, 0.0f), 1.0f);
#pragma unroll
        for (int j = 0; j < KK; j++)
            g_w[layer][k * KK + j] = b * row[j] * inv + ((j == k) ? 1.0f : 0.0f);
    }
}

// ---------------------------------------------------------------------------
// Kernel 3: out[l,k,n] = last[l,k,n] + sum_j W[l,k,j] * deltas[l,j,n]
// R3 structure (plain loads/stores, NO cache hints) but DESCENDING chunk
// order: gram's final iterations touched the high-n region of deltas, which
// is still L2-resident across the launch boundary (L2 survives launches;
// only L1 is flushed). Reading high-n first converts those delta re-reads
// into L2 hits before our own store traffic evicts them.
// grid = (OBLK, LL), block = 256, float4 streaming.
// ---------------------------------------------------------------------------
__global__ __launch_bounds__(256) void out_kernel(const float* __restrict__ last,
                                                  const float* __restrict__ deltas,
                                                  float* __restrict__ out) {
    const int layer = blockIdx.y;
    __shared__ float w[KK * KK];
    const int tid = threadIdx.x;
    if (tid < KK * KK) w[tid] = g_w[layer][tid];
    __syncthreads();

    const size_t off = (size_t)layer * KK * NN;
    const float4* __restrict__ d4 = reinterpret_cast<const float4*>(deltas + off);
    const float4* __restrict__ l4 = reinterpret_cast<const float4*>(last + off);
    float4* __restrict__ o4 = reinterpret_cast<float4*>(out + off);

    const int R = NN / 4;                 // 262144
    const int stride = OBLK * 256;        // 65536
    const int iters = R / stride;         // 4
    const int idx = blockIdx.x * 256 + tid;

#pragma unroll
    for (int it = iters - 1; it >= 0; it--) {   // descending: harvest L2 tail
        const int n4 = idx + it * stride;
        float4 d[KK];
#pragma unroll
        for (int j = 0; j < KK; j++)
            d[j] = d4[(size_t)j * R + n4];

#pragma unroll
        for (int k = 0; k < KK; k++) {
            float4 acc = l4[(size_t)k * R + n4];
#pragma unroll
            for (int j = 0; j < KK; j++) {
                const float wv = w[k * KK + j];
                acc.x = fmaf(wv, d[j].x, acc.x);
                acc.y = fmaf(wv, d[j].y, acc.y);
                acc.z = fmaf(wv, d[j].z, acc.z);
                acc.w = fmaf(wv, d[j].w, acc.w);
            }
            o4[(size_t)k * R + n4] = acc;
        }
    }
}

extern "C" void kernel_launch(void* const* d_in, const int* in_sizes, int n_in,
                              void* d_out, int out_size) {
    const float* last   = (const float*)d_in[0];
    const float* deltas = (const float*)d_in[1];
    const float* beta   = (const float*)d_in[2];
    float* out = (float*)d_out;

    dim3 ggrid(GBLK, LL);
    gram_kernel<<<ggrid, 256>>>(deltas);

    finish_kernel<<<LL, 64>>>(beta);

    dim3 ogrid(OBLK, LL);
    out_kernel<<<ogrid, 256>>>(last, deltas, out);
}